// round 3
// baseline (speedup 1.0000x reference)
#include <cuda_runtime.h>

#define NTOK 4096
#define CDIM 768
#define C3   2304
#define TPL  16
#define NH   12
#define HD   64

__device__ float g_qkv_w[C3 * CDIM];
__device__ float g_qkv[NTOK * C3];
__device__ float g_att[NTOK * CDIM];

// ---------------------------------------------------------------------------
// helpers
// ---------------------------------------------------------------------------
__device__ __forceinline__ unsigned f2tf(float x) {
    unsigned r;
    asm("cvt.rna.tf32.f32 %0, %1;" : "=r"(r) : "f"(x));
    return r;
}
__device__ __forceinline__ float f2tff(float x) { return __uint_as_float(f2tf(x)); }

__device__ __forceinline__ void split_tf(unsigned raw, unsigned& hi, unsigned& lo) {
    float x = __uint_as_float(raw);
    unsigned h = f2tf(x);
    float l = x - __uint_as_float(h);
    hi = h;
    lo = f2tf(l);
}

__device__ __forceinline__ void ldsm4(unsigned& r0, unsigned& r1, unsigned& r2, unsigned& r3,
                                      unsigned addr) {
    asm volatile("ldmatrix.sync.aligned.m8n8.x4.shared.b16 {%0,%1,%2,%3}, [%4];"
                 : "=r"(r0), "=r"(r1), "=r"(r2), "=r"(r3) : "r"(addr));
}
__device__ __forceinline__ void mma_tf32(float* d, const unsigned* a, unsigned b0, unsigned b1) {
    asm volatile(
        "mma.sync.aligned.m16n8k8.row.col.f32.tf32.tf32.f32 "
        "{%0,%1,%2,%3},{%4,%5,%6,%7},{%8,%9},{%0,%1,%2,%3};"
        : "+f"(d[0]), "+f"(d[1]), "+f"(d[2]), "+f"(d[3])
        : "r"(a[0]), "r"(a[1]), "r"(a[2]), "r"(a[3]), "r"(b0), "r"(b1));
}
__device__ __forceinline__ unsigned smem_u32(const void* p) {
    return (unsigned)__cvta_generic_to_shared(p);
}
__device__ __forceinline__ void cpasync16(unsigned dst, const void* src) {
    asm volatile("cp.async.cg.shared.global [%0], [%1], 16;" :: "r"(dst), "l"(src));
}

// ---------------------------------------------------------------------------
// Kernel 1: template reduce
// ---------------------------------------------------------------------------
__global__ void k_build_w(const float* __restrict__ tpl, const float* __restrict__ coef) {
    __shared__ float w[TPL];
    if (threadIdx.x < TPL)
        w[threadIdx.x] = 0.5f * (coef[threadIdx.x] + coef[TPL + threadIdx.x]);
    __syncthreads();
    const int TOT = C3 * CDIM / 4;
    int idx = blockIdx.x * blockDim.x + threadIdx.x;
    if (idx >= TOT) return;
    const float4* t4 = (const float4*)tpl;
    float4 acc = make_float4(0.f, 0.f, 0.f, 0.f);
#pragma unroll
    for (int t = 0; t < TPL; t++) {
        float4 v = t4[(size_t)t * TOT + idx];
        float wt = w[t];
        acc.x = fmaf(wt, v.x, acc.x);
        acc.y = fmaf(wt, v.y, acc.y);
        acc.z = fmaf(wt, v.z, acc.z);
        acc.w = fmaf(wt, v.w, acc.w);
    }
    ((float4*)g_qkv_w)[idx] = acc;
}

// ---------------------------------------------------------------------------
// split-tf32 tensor-core GEMM (TN): Y = A @ B^T + bias.  Near-fp32 accuracy.
// 128x128 tile, BK=16, 8 warps, cp.async double-buffered raw-fp32 staging,
// in-register hi/lo split, 3 MMAs per fragment pair (hi*hi + lo*hi + hi*lo).
// ---------------------------------------------------------------------------
__device__ __forceinline__ void gemm_tn_mma(const float* __restrict__ A,
                                            const float* __restrict__ Bm,
                                            const float* __restrict__ bias,
                                            float* __restrict__ Y,
                                            int Nd, int K) {
    __shared__ __align__(16) float As[2][128 * 20];
    __shared__ __align__(16) float Bs[2][128 * 20];

    int tid = threadIdx.x;
    int lane = tid & 31;
    int w = tid >> 5;
    int wm = w >> 1;
    int wn = w & 1;
    int g = lane >> 2, q = lane & 3;

    int m0 = blockIdx.y * 128;
    int n0 = blockIdx.x * 128;

    float acc[2][8][4];
#pragma unroll
    for (int mi = 0; mi < 2; mi++)
#pragma unroll
        for (int nt = 0; nt < 8; nt++)
#pragma unroll
            for (int e = 0; e < 4; e++) acc[mi][nt][e] = 0.f;

    // staging: 512 x 16B chunks per operand tile, 2 per thread
    int row0 = tid >> 2, q0c = tid & 3;
    int row1 = (tid + 256) >> 2, q1c = tid & 3;
    unsigned asBase = smem_u32(As);
    unsigned bsBase = smem_u32(Bs);

    // ldmatrix bases
    int roffA = ((lane >> 3) & 1) * 8 + (lane & 7);
    int coffA = (lane >> 4) * 4;
    int roffB = ((lane >> 4) & 1) * 8 + (lane & 7);
    int coffB = ((lane >> 3) & 1) * 4;
    unsigned aAddr = asBase + (((32 * wm + roffA) * 20 + coffA) << 2);
    unsigned bAddr = bsBase + (((64 * wn + roffB) * 20 + coffB) << 2);
    const unsigned BUF = 128 * 20 * 4;

    const int NT = K >> 4;

    // prologue: tile 0 -> buf 0
    {
        const float* a0 = A + (size_t)(m0 + row0) * K + 4 * q0c;
        const float* a1 = A + (size_t)(m0 + row1) * K + 4 * q1c;
        const float* b0 = Bm + (size_t)(n0 + row0) * K + 4 * q0c;
        const float* b1 = Bm + (size_t)(n0 + row1) * K + 4 * q1c;
        cpasync16(asBase + ((row0 * 20 + 4 * q0c) << 2), a0);
        cpasync16(asBase + ((row1 * 20 + 4 * q1c) << 2), a1);
        cpasync16(bsBase + ((row0 * 20 + 4 * q0c) << 2), b0);
        cpasync16(bsBase + ((row1 * 20 + 4 * q1c) << 2), b1);
        asm volatile("cp.async.commit_group;");
    }

    for (int it = 0; it < NT; it++) {
        int cur = it & 1;
        if (it + 1 < NT) {
            int nxt = (it + 1) & 1;
            int k0 = (it + 1) << 4;
            const float* a0 = A + (size_t)(m0 + row0) * K + k0 + 4 * q0c;
            const float* a1 = A + (size_t)(m0 + row1) * K + k0 + 4 * q1c;
            const float* b0 = Bm + (size_t)(n0 + row0) * K + k0 + 4 * q0c;
            const float* b1 = Bm + (size_t)(n0 + row1) * K + k0 + 4 * q1c;
            cpasync16(asBase + nxt * BUF + ((row0 * 20 + 4 * q0c) << 2), a0);
            cpasync16(asBase + nxt * BUF + ((row1 * 20 + 4 * q1c) << 2), a1);
            cpasync16(bsBase + nxt * BUF + ((row0 * 20 + 4 * q0c) << 2), b0);
            cpasync16(bsBase + nxt * BUF + ((row1 * 20 + 4 * q1c) << 2), b1);
            asm volatile("cp.async.commit_group;");
            asm volatile("cp.async.wait_group 1;");
        } else {
            asm volatile("cp.async.wait_group 0;");
        }
        __syncthreads();

        unsigned ac = aAddr + cur * BUF;
        unsigned bc = bAddr + cur * BUF;
#pragma unroll
        for (int ks = 0; ks < 2; ks++) {
            unsigned araw[2][4], ahi[2][4], alo[2][4];
            ldsm4(araw[0][0], araw[0][1], araw[0][2], araw[0][3], ac + ks * 32);
            ldsm4(araw[1][0], araw[1][1], araw[1][2], araw[1][3], ac + 16 * 20 * 4 + ks * 32);
#pragma unroll
            for (int mi = 0; mi < 2; mi++)
#pragma unroll
                for (int e = 0; e < 4; e++) split_tf(araw[mi][e], ahi[mi][e], alo[mi][e]);
#pragma unroll
            for (int ntp = 0; ntp < 4; ntp++) {
                unsigned braw[4], bhi[4], blo[4];
                ldsm4(braw[0], braw[1], braw[2], braw[3], bc + ntp * (16 * 20 * 4) + ks * 32);
#pragma unroll
                for (int e = 0; e < 4; e++) split_tf(braw[e], bhi[e], blo[e]);
#pragma unroll
                for (int mi = 0; mi < 2; mi++) {
                    mma_tf32(acc[mi][2 * ntp + 0], ahi[mi], bhi[0], bhi[1]);
                    mma_tf32(acc[mi][2 * ntp + 0], alo[mi], bhi[0], bhi[1]);
                    mma_tf32(acc[mi][2 * ntp + 0], ahi[mi], blo[0], blo[1]);
                    mma_tf32(acc[mi][2 * ntp + 1], ahi[mi], bhi[2], bhi[3]);
                    mma_tf32(acc[mi][2 * ntp + 1], alo[mi], bhi[2], bhi[3]);
                    mma_tf32(acc[mi][2 * ntp + 1], ahi[mi], blo[2], blo[3]);
                }
            }
        }
        __syncthreads();
    }

#pragma unroll
    for (int mi = 0; mi < 2; mi++) {
        int r0 = m0 + 32 * wm + 16 * mi + g;
        int r1 = r0 + 8;
#pragma unroll
        for (int nt = 0; nt < 8; nt++) {
            int n = n0 + 64 * wn + 8 * nt + 2 * q;
            float2 b2 = *(const float2*)(bias + n);
            float2 v0, v1;
            v0.x = acc[mi][nt][0] + b2.x; v0.y = acc[mi][nt][1] + b2.y;
            v1.x = acc[mi][nt][2] + b2.x; v1.y = acc[mi][nt][3] + b2.y;
            *(float2*)(Y + (size_t)r0 * Nd + n) = v0;
            *(float2*)(Y + (size_t)r1 * Nd + n) = v1;
        }
    }
}

__global__ void __launch_bounds__(256) k_gemm_qkv(const float* __restrict__ x,
                                                  const float* __restrict__ qb) {
    gemm_tn_mma(x, g_qkv_w, qb, g_qkv, C3, CDIM);
}
__global__ void __launch_bounds__(256) k_gemm_proj(const float* __restrict__ pw,
                                                   const float* __restrict__ pb,
                                                   float* __restrict__ out) {
    gemm_tn_mma(g_att, pw, pb, out, CDIM, CDIM);
}

// ---------------------------------------------------------------------------
// Flash attention, tf32 tensor cores (unchanged math; 2 CTAs/SM for overlap).
// ---------------------------------------------------------------------------
__global__ void __launch_bounds__(256, 2) k_flash() {
    extern __shared__ float sm[];
    float* Ks = sm;                 // [64][68]
    float* Vt = sm + 64 * 68;       // [64][68] transposed
    float* Ps = sm + 2 * 64 * 68;   // [128][68] Q staging, then warp-private P

    int tid = threadIdx.x;
    int lane = tid & 31;
    int w = tid >> 5;
    int g = lane >> 2, q = lane & 3;
    int h = blockIdx.y;
    int q0 = blockIdx.x * 128;

#pragma unroll
    for (int l = 0; l < 8; l++) {
        int row = tid & 127;
        int qd = (tid >> 7) + 2 * l;
        float4 v = *(const float4*)(g_qkv + (size_t)(q0 + row) * C3 + h * HD + 4 * qd);
        float* dst = Ps + row * 68 + 4 * qd;
        dst[0] = f2tff(v.x * 0.125f);
        dst[1] = f2tff(v.y * 0.125f);
        dst[2] = f2tff(v.z * 0.125f);
        dst[3] = f2tff(v.w * 0.125f);
    }
    __syncthreads();

    int roffA = ((lane >> 3) & 1) * 8 + (lane & 7);
    int coffA = (lane >> 4) * 4;
    unsigned aAddr = smem_u32(Ps + (16 * w + roffA) * 68 + coffA);
    unsigned qf[8][4];
#pragma unroll
    for (int ks = 0; ks < 8; ks++)
        ldsm4(qf[ks][0], qf[ks][1], qf[ks][2], qf[ks][3], aAddr + ks * 32);

    int roffB = ((lane >> 4) & 1) * 8 + (lane & 7);
    int coffB = ((lane >> 3) & 1) * 4;
    unsigned kAddr = smem_u32(Ks + roffB * 68 + coffB);
    unsigned vAddr = smem_u32(Vt + roffB * 68 + coffB);

    float o[8][4];
#pragma unroll
    for (int nt = 0; nt < 8; nt++)
#pragma unroll
        for (int e = 0; e < 4; e++) o[nt][e] = 0.f;
    float mi0 = -1e30f, mi1 = -1e30f, li0 = 0.f, li1 = 0.f;

    float* p0base = Ps + (16 * w + g) * 68 + 2 * q;
    float* p1base = Ps + (16 * w + 8 + g) * 68 + 2 * q;

    for (int kb = 0; kb < NTOK / 64; kb++) {
        __syncthreads();
        int k0 = kb * 64;
#pragma unroll
        for (int l = 0; l < 4; l++) {
            int row = tid & 63;
            int qd = (tid >> 6) + 4 * l;
            float4 kv = *(const float4*)(g_qkv + (size_t)(k0 + row) * C3 + CDIM + h * HD + 4 * qd);
            float* dk = Ks + row * 68 + 4 * qd;
            dk[0] = f2tff(kv.x); dk[1] = f2tff(kv.y); dk[2] = f2tff(kv.z); dk[3] = f2tff(kv.w);
            float4 vv = *(const float4*)(g_qkv + (size_t)(k0 + row) * C3 + 2 * CDIM + h * HD + 4 * qd);
            Vt[(4 * qd + 0) * 68 + row] = f2tff(vv.x);
            Vt[(4 * qd + 1) * 68 + row] = f2tff(vv.y);
            Vt[(4 * qd + 2) * 68 + row] = f2tff(vv.z);
            Vt[(4 * qd + 3) * 68 + row] = f2tff(vv.w);
        }
        __syncthreads();

        float s[8][4];
#pragma unroll
        for (int nt = 0; nt < 8; nt++)
#pragma unroll
            for (int e = 0; e < 4; e++) s[nt][e] = 0.f;
#pragma unroll
        for (int ks = 0; ks < 8; ks++) {
#pragma unroll
            for (int ntp = 0; ntp < 4; ntp++) {
                unsigned b0, b1, b2, b3;
                ldsm4(b0, b1, b2, b3, kAddr + ntp * (16 * 68 * 4) + ks * 32);
                mma_tf32(s[2 * ntp + 0], qf[ks], b0, b1);
                mma_tf32(s[2 * ntp + 1], qf[ks], b2, b3);
            }
        }

        float mx0 = -1e30f, mx1 = -1e30f;
#pragma unroll
        for (int nt = 0; nt < 8; nt++) {
            mx0 = fmaxf(mx0, fmaxf(s[nt][0], s[nt][1]));
            mx1 = fmaxf(mx1, fmaxf(s[nt][2], s[nt][3]));
        }
        mx0 = fmaxf(mx0, __shfl_xor_sync(0xffffffffu, mx0, 1));
        mx0 = fmaxf(mx0, __shfl_xor_sync(0xffffffffu, mx0, 2));
        mx1 = fmaxf(mx1, __shfl_xor_sync(0xffffffffu, mx1, 1));
        mx1 = fmaxf(mx1, __shfl_xor_sync(0xffffffffu, mx1, 2));
        float mn0 = fmaxf(mi0, mx0);
        float mn1 = fmaxf(mi1, mx1);
        float al0 = __expf(mi0 - mn0);
        float al1 = __expf(mi1 - mn1);
        mi0 = mn0; mi1 = mn1;

        float sum0 = 0.f, sum1 = 0.f;
#pragma unroll
        for (int nt = 0; nt < 8; nt++) {
            s[nt][0] = __expf(s[nt][0] - mn0);
            s[nt][1] = __expf(s[nt][1] - mn0);
            s[nt][2] = __expf(s[nt][2] - mn1);
            s[nt][3] = __expf(s[nt][3] - mn1);
            sum0 += s[nt][0] + s[nt][1];
            sum1 += s[nt][2] + s[nt][3];
        }
        sum0 += __shfl_xor_sync(0xffffffffu, sum0, 1);
        sum0 += __shfl_xor_sync(0xffffffffu, sum0, 2);
        sum1 += __shfl_xor_sync(0xffffffffu, sum1, 1);
        sum1 += __shfl_xor_sync(0xffffffffu, sum1, 2);
        li0 = li0 * al0 + sum0;
        li1 = li1 * al1 + sum1;

#pragma unroll
        for (int nt = 0; nt < 8; nt++) {
            o[nt][0] *= al0; o[nt][1] *= al0;
            o[nt][2] *= al1; o[nt][3] *= al1;
        }

#pragma unroll
        for (int nt = 0; nt < 8; nt++) {
            float2 v0; v0.x = f2tff(s[nt][0]); v0.y = f2tff(s[nt][1]);
            float2 v1; v1.x = f2tff(s[nt][2]); v1.y = f2tff(s[nt][3]);
            *(float2*)(p0base + 8 * nt) = v0;
            *(float2*)(p1base + 8 * nt) = v1;
        }
        __syncwarp();

#pragma unroll
        for (int ks = 0; ks < 8; ks++) {
            unsigned pf[4];
            ldsm4(pf[0], pf[1], pf[2], pf[3], aAddr + ks * 32);
#pragma unroll
            for (int ntp = 0; ntp < 4; ntp++) {
                unsigned b0, b1, b2, b3;
                ldsm4(b0, b1, b2, b3, vAddr + ntp * (16 * 68 * 4) + ks * 32);
                mma_tf32(o[2 * ntp + 0], pf, b0, b1);
                mma_tf32(o[2 * ntp + 1], pf, b2, b3);
            }
        }
    }

    float inv0 = 1.f / li0;
    float inv1 = 1.f / li1;
    int r0 = q0 + 16 * w + g;
    int r1 = r0 + 8;
#pragma unroll
    for (int nt = 0; nt < 8; nt++) {
        int c = h * HD + 8 * nt + 2 * q;
        float2 v0; v0.x = o[nt][0] * inv0; v0.y = o[nt][1] * inv0;
        float2 v1; v1.x = o[nt][2] * inv1; v1.y = o[nt][3] * inv1;
        *(float2*)(g_att + (size_t)r0 * CDIM + c) = v0;
        *(float2*)(g_att + (size_t)r1 * CDIM + c) = v1;
    }
}

// ---------------------------------------------------------------------------
extern "C" void kernel_launch(void* const* d_in, const int* in_sizes, int n_in,
                              void* d_out, int out_size) {
    const float* x         = (const float*)d_in[0];
    const float* templates = (const float*)d_in[1];
    const float* coeffs    = (const float*)d_in[2];
    const float* qkv_bias  = (const float*)d_in[3];
    const float* proj_w    = (const float*)d_in[4];
    const float* proj_b    = (const float*)d_in[5];
    float* out = (float*)d_out;

    k_build_w<<<(C3 * CDIM / 4 + 255) / 256, 256>>>(templates, coeffs);

    k_gemm_qkv<<<dim3(C3 / 128, NTOK / 128), 256>>>(x, qkv_bias);

    int smem = 256 * 68 * (int)sizeof(float);   // 69632 B
    cudaFuncSetAttribute(k_flash, cudaFuncAttributeMaxDynamicSharedMemorySize, smem);
    k_flash<<<dim3(NTOK / 128, NH), 256, smem>>>();

    k_gemm_proj<<<dim3(CDIM / 128, NTOK / 128), 256>>>(proj_w, proj_b, out);
}